// round 2
// baseline (speedup 1.0000x reference)
#include <cuda_runtime.h>
#include <cuda_bf16.h>
#include <math.h>

// ---------------------------------------------------------------------------
// Shapes (fixed by problem): B=16, N=512, D=256, H=8, DK=32, C=16
// ---------------------------------------------------------------------------
#define BB 16
#define NN 512
#define DD 256
#define HH 8
#define DKH 32
#define CC 16

// ---------------------------------------------------------------------------
// Scratch (device globals; no allocation allowed)
// ---------------------------------------------------------------------------
__device__ float g_bufQ[BB * NN * DD];
__device__ float g_bufK[BB * NN * DD];
__device__ float g_bufV[BB * NN * DD];
__device__ float g_bufO[BB * NN * DD];
__device__ float g_bufX[BB * NN * DD];
__device__ float g_aggrg[BB * DD];
__device__ float g_ares[BB * DD];
__device__ float g_rbias[BB * DD];
__device__ float g_G[BB * CC * DD];
__device__ float g_CNT[BB * CC];

__device__ __forceinline__ float gelu_f(float x) {
    return 0.5f * x * (1.0f + erff(x * 0.7071067811865475f));
}

// ---------------------------------------------------------------------------
// Generic SGEMM: C[M,N] = act_out( act_in(A)[M,K] @ W[K,N] + bias )
//   AIN:  0 = identity, 1 = gelu applied to A elements
//   AOUT: 0 = identity, 1 = gelu applied to result
//   BMODE: 0 = none, 1 = per-column bias[N], 2 = per-(row/512)-batch bias[16][N]
// BM=BN=64, BK=16, 256 threads, 4x4 micro-tile.
// Requires: N % 64 == 0, K % 16 == 0, rows guarded by M.
// ---------------------------------------------------------------------------
#define BM 64
#define BN 64
#define BK 16

template <int AIN, int AOUT, int BMODE>
__global__ __launch_bounds__(256) void gemm_kernel(
    const float* __restrict__ A, const float* __restrict__ W,
    const float* __restrict__ bias, float* __restrict__ C,
    int M, int N, int K)
{
    __shared__ float As[BK][BM + 4];
    __shared__ float Ws[BK][BN + 4];

    const int bm = blockIdx.x * BM;
    const int bn = blockIdx.y * BN;
    const int t  = threadIdx.x;
    const int tx = t & 15;        // 0..15  -> n = tx*4
    const int ty = t >> 4;        // 0..15  -> m = ty*4

    const int la_m = t >> 2;          // 0..63
    const int la_k = (t & 3) * 4;     // 0,4,8,12
    const int lw_k = t >> 4;          // 0..15
    const int lw_n = (t & 15) * 4;    // 0..60

    float acc[4][4];
    #pragma unroll
    for (int i = 0; i < 4; i++)
        #pragma unroll
        for (int j = 0; j < 4; j++) acc[i][j] = 0.0f;

    for (int k0 = 0; k0 < K; k0 += BK) {
        // load A tile (64 x 16), transposed into smem
        float4 av = make_float4(0.f, 0.f, 0.f, 0.f);
        if (bm + la_m < M)
            av = *(const float4*)&A[(size_t)(bm + la_m) * K + k0 + la_k];
        if (AIN) {
            av.x = gelu_f(av.x); av.y = gelu_f(av.y);
            av.z = gelu_f(av.z); av.w = gelu_f(av.w);
        }
        As[la_k + 0][la_m] = av.x;
        As[la_k + 1][la_m] = av.y;
        As[la_k + 2][la_m] = av.z;
        As[la_k + 3][la_m] = av.w;

        // load W tile (16 x 64)
        float4 wv = *(const float4*)&W[(size_t)(k0 + lw_k) * N + bn + lw_n];
        *(float4*)&Ws[lw_k][lw_n] = wv;

        __syncthreads();

        #pragma unroll
        for (int k = 0; k < BK; k++) {
            float4 a = *(const float4*)&As[k][ty * 4];
            float4 b = *(const float4*)&Ws[k][tx * 4];
            acc[0][0] += a.x * b.x; acc[0][1] += a.x * b.y; acc[0][2] += a.x * b.z; acc[0][3] += a.x * b.w;
            acc[1][0] += a.y * b.x; acc[1][1] += a.y * b.y; acc[1][2] += a.y * b.z; acc[1][3] += a.y * b.w;
            acc[2][0] += a.z * b.x; acc[2][1] += a.z * b.y; acc[2][2] += a.z * b.z; acc[2][3] += a.z * b.w;
            acc[3][0] += a.w * b.x; acc[3][1] += a.w * b.y; acc[3][2] += a.w * b.z; acc[3][3] += a.w * b.w;
        }
        __syncthreads();
    }

    #pragma unroll
    for (int i = 0; i < 4; i++) {
        int row = bm + ty * 4 + i;
        if (row >= M) continue;
        #pragma unroll
        for (int j = 0; j < 4; j++) {
            int col = bn + tx * 4 + j;
            float v = acc[i][j];
            if (BMODE == 1) v += bias[col];
            if (BMODE == 2) v += bias[(row >> 9) * N + col];
            if (AOUT) v = gelu_f(v);
            C[(size_t)row * N + col] = v;
        }
    }
}

// ---------------------------------------------------------------------------
// Fused attention: per (block) 64 queries of one (b,h). Full 512-wide score
// rows held in dynamic shared memory (no HBM round-trip for scores).
// grid (N/64, H, B), 256 threads.
// Layout of Q/K/V/O: [B*N, 256] with head h at columns h*32..h*32+31.
// ---------------------------------------------------------------------------
#define SP 516   // padded score row (516 % 32 == 4 -> spreads banks)
#define ATTN_SMEM_FLOATS (2 * 64 * 33 + 64 * SP)
#define ATTN_SMEM_BYTES  (ATTN_SMEM_FLOATS * 4)

__global__ __launch_bounds__(256) void attn_kernel(
    const float* __restrict__ Qp, const float* __restrict__ Kp,
    const float* __restrict__ Vp, float* __restrict__ Op)
{
    extern __shared__ float sm[];
    float* qs = sm;                 // [64][33]
    float* ks = sm + 64 * 33;       // [64][33]  (K tiles, then reused for V tiles)
    float* sc = sm + 2 * 64 * 33;   // [64][SP]

    const int t  = threadIdx.x;
    const int qb = blockIdx.x * 64;
    const int h  = blockIdx.y;
    const int b  = blockIdx.z;
    const float scale = 0.17677669529663688f;  // 1/sqrt(32)

    const size_t baseQ  = ((size_t)(b * NN + qb)) * DD + h * DKH;
    const size_t baseKV = ((size_t)(b * NN)) * DD + h * DKH;

    // load Q (pre-scaled)
    for (int i = t; i < 64 * 32; i += 256) {
        int r = i >> 5, d = i & 31;
        qs[r * 33 + d] = Qp[baseQ + (size_t)r * DD + d] * scale;
    }

    const int tx = t & 15, ty = t >> 4;

    // ---- scores = Q @ K^T ----
    for (int kt = 0; kt < 8; kt++) {
        const int kb = kt * 64;
        __syncthreads();
        for (int i = t; i < 64 * 32; i += 256) {
            int r = i >> 5, d = i & 31;
            ks[r * 33 + d] = Kp[baseKV + (size_t)(kb + r) * DD + d];
        }
        __syncthreads();
        float acc[4][4];
        #pragma unroll
        for (int i = 0; i < 4; i++)
            #pragma unroll
            for (int j = 0; j < 4; j++) acc[i][j] = 0.0f;
        #pragma unroll
        for (int d = 0; d < 32; d++) {
            float a0 = qs[(ty * 4 + 0) * 33 + d];
            float a1 = qs[(ty * 4 + 1) * 33 + d];
            float a2 = qs[(ty * 4 + 2) * 33 + d];
            float a3 = qs[(ty * 4 + 3) * 33 + d];
            float b0 = ks[(tx * 4 + 0) * 33 + d];
            float b1 = ks[(tx * 4 + 1) * 33 + d];
            float b2 = ks[(tx * 4 + 2) * 33 + d];
            float b3 = ks[(tx * 4 + 3) * 33 + d];
            acc[0][0] += a0 * b0; acc[0][1] += a0 * b1; acc[0][2] += a0 * b2; acc[0][3] += a0 * b3;
            acc[1][0] += a1 * b0; acc[1][1] += a1 * b1; acc[1][2] += a1 * b2; acc[1][3] += a1 * b3;
            acc[2][0] += a2 * b0; acc[2][1] += a2 * b1; acc[2][2] += a2 * b2; acc[2][3] += a2 * b3;
            acc[3][0] += a3 * b0; acc[3][1] += a3 * b1; acc[3][2] += a3 * b2; acc[3][3] += a3 * b3;
        }
        #pragma unroll
        for (int i = 0; i < 4; i++)
            #pragma unroll
            for (int j = 0; j < 4; j++)
                sc[(ty * 4 + i) * SP + kb + tx * 4 + j] = acc[i][j];
    }
    __syncthreads();

    // ---- row softmax (8 warps x 8 rows) ----
    {
        const int w = t >> 5, lane = t & 31;
        for (int r = w * 8; r < w * 8 + 8; r++) {
            float mx = -1e30f;
            for (int i = lane; i < 512; i += 32) mx = fmaxf(mx, sc[r * SP + i]);
            #pragma unroll
            for (int o = 16; o; o >>= 1) mx = fmaxf(mx, __shfl_xor_sync(0xFFFFFFFFu, mx, o));
            float s = 0.0f;
            for (int i = lane; i < 512; i += 32) {
                float e = expf(sc[r * SP + i] - mx);
                sc[r * SP + i] = e;
                s += e;
            }
            #pragma unroll
            for (int o = 16; o; o >>= 1) s += __shfl_xor_sync(0xFFFFFFFFu, s, o);
            float inv = 1.0f / s;
            for (int i = lane; i < 512; i += 32) sc[r * SP + i] *= inv;
        }
    }
    __syncthreads();

    // ---- O = P @ V ----
    const int q  = t >> 2;          // 0..63
    const int dg = (t & 3) * 8;     // 0,8,16,24
    float o[8];
    #pragma unroll
    for (int j = 0; j < 8; j++) o[j] = 0.0f;

    for (int kt = 0; kt < 8; kt++) {
        const int kb = kt * 64;
        __syncthreads();
        for (int i = t; i < 64 * 32; i += 256) {
            int r = i >> 5, d = i & 31;
            ks[r * 33 + d] = Vp[baseKV + (size_t)(kb + r) * DD + d];
        }
        __syncthreads();
        #pragma unroll 4
        for (int kk = 0; kk < 64; kk++) {
            float p = sc[q * SP + kb + kk];
            #pragma unroll
            for (int j = 0; j < 8; j++) o[j] += p * ks[kk * 33 + dg + j];
        }
    }
    #pragma unroll
    for (int j = 0; j < 8; j++)
        Op[baseQ + (size_t)q * DD + dg + j] = o[j];
}

// ---------------------------------------------------------------------------
// aggr = gelu(mean over N)  : grid (B), 256 threads (thread = column d)
// ---------------------------------------------------------------------------
__global__ __launch_bounds__(256) void colmean_gelu_kernel(
    const float* __restrict__ X, float* __restrict__ out)
{
    const int b = blockIdx.x;
    const int d = threadIdx.x;
    float s = 0.0f;
    const float* base = X + (size_t)b * NN * DD + d;
    for (int n = 0; n < NN; n++) s += base[(size_t)n * DD];
    out[b * DD + d] = gelu_f(s * (1.0f / (float)NN));
}

// ---------------------------------------------------------------------------
// Class sums g[b][c][:] = sum_{n: lab=c} f[b][n][:]  and counts.
// grid (B), 256 threads (thread = column d)
// ---------------------------------------------------------------------------
__global__ __launch_bounds__(256) void class_sum_kernel(
    const float* __restrict__ F, const int* __restrict__ lab,
    float* __restrict__ G, float* __restrict__ CNT)
{
    __shared__ float gs[CC * DD];
    __shared__ float cs[CC];
    const int b = blockIdx.x;
    const int t = threadIdx.x;
    for (int i = t; i < CC * DD; i += 256) gs[i] = 0.0f;
    if (t < CC) cs[t] = 0.0f;
    __syncthreads();
    for (int n = 0; n < NN; n++) {
        int c = lab[b * NN + n];
        gs[c * DD + t] += F[((size_t)b * NN + n) * DD + t];
        if (t == 0) cs[c] += 1.0f;
    }
    __syncthreads();
    for (int i = t; i < CC * DD; i += 256) G[(size_t)b * CC * DD + i] = gs[i];
    if (t < CC) CNT[b * CC + t] = cs[t];
}

// ---------------------------------------------------------------------------
// out[b][n][c] = (f_n . g_c - [lab_n==c] * ||f_n||^2) / (counts[c] - [lab_n==c])
// grid (N, B), 256 threads (8 warps; warp w -> classes 2w, 2w+1)
// ---------------------------------------------------------------------------
__global__ __launch_bounds__(256) void proto_out_kernel(
    const float* __restrict__ F, const float* __restrict__ G,
    const float* __restrict__ CNT, const int* __restrict__ lab,
    float* __restrict__ out)
{
    __shared__ float fs[DD];
    const int n = blockIdx.x;
    const int b = blockIdx.y;
    const int t = threadIdx.x;
    fs[t] = F[((size_t)b * NN + n) * DD + t];
    __syncthreads();

    const int w = t >> 5, lane = t & 31;
    float sd = 0.0f;
    for (int i = lane; i < DD; i += 32) sd += fs[i] * fs[i];
    #pragma unroll
    for (int o = 16; o; o >>= 1) sd += __shfl_xor_sync(0xFFFFFFFFu, sd, o);

    const int labn = lab[b * NN + n];
    #pragma unroll
    for (int cc = 0; cc < 2; cc++) {
        const int c = w * 2 + cc;
        const float* g = G + (size_t)b * CC * DD + c * DD;
        float dp = 0.0f;
        for (int i = lane; i < DD; i += 32) dp += fs[i] * g[i];
        #pragma unroll
        for (int o = 16; o; o >>= 1) dp += __shfl_xor_sync(0xFFFFFFFFu, dp, o);
        if (lane == 0) {
            float same = (labn == c) ? 1.0f : 0.0f;
            out[((size_t)b * NN + n) * CC + c] =
                (dp - same * sd) / (CNT[b * CC + c] - same);
        }
    }
}

// ---------------------------------------------------------------------------
// Host orchestration
// ---------------------------------------------------------------------------
extern "C" void kernel_launch(void* const* d_in, const int* in_sizes, int n_in,
                              void* d_out, int out_size)
{
    const float* E    = (const float*)d_in[0];
    const int*   lab  = (const int*)  d_in[1];
    const float* Wq0  = (const float*)d_in[2];
    const float* Wk0  = (const float*)d_in[3];
    const float* Wv0  = (const float*)d_in[4];
    const float* Wo0  = (const float*)d_in[5];
    const float* Wq1  = (const float*)d_in[6];
    const float* Wk1  = (const float*)d_in[7];
    const float* Wv1  = (const float*)d_in[8];
    const float* Wo1  = (const float*)d_in[9];
    const float* resW = (const float*)d_in[10];
    const float* resb = (const float*)d_in[11];
    const float* ffW1 = (const float*)d_in[12];
    const float* ffb1 = (const float*)d_in[13];
    const float* ffW2 = (const float*)d_in[14];
    const float* ffb2 = (const float*)d_in[15];
    float* out = (float*)d_out;

    float *bQ, *bK, *bV, *bO, *bX, *aggrg, *ares, *rbias, *G, *CNT;
    cudaGetSymbolAddress((void**)&bQ,    g_bufQ);
    cudaGetSymbolAddress((void**)&bK,    g_bufK);
    cudaGetSymbolAddress((void**)&bV,    g_bufV);
    cudaGetSymbolAddress((void**)&bO,    g_bufO);
    cudaGetSymbolAddress((void**)&bX,    g_bufX);
    cudaGetSymbolAddress((void**)&aggrg, g_aggrg);
    cudaGetSymbolAddress((void**)&ares,  g_ares);
    cudaGetSymbolAddress((void**)&rbias, g_rbias);
    cudaGetSymbolAddress((void**)&G,     g_G);
    cudaGetSymbolAddress((void**)&CNT,   g_CNT);

    cudaFuncSetAttribute(attn_kernel,
                         cudaFuncAttributeMaxDynamicSharedMemorySize,
                         ATTN_SMEM_BYTES);

    const int M = BB * NN;                 // 8192
    dim3 gBig(M / BM, DD / BN);            // (128, 4)
    dim3 gSmall(1, DD / BN);               // (1, 4)
    dim3 gAttn(NN / 64, HH, BB);           // (8, 8, 16)

    // ---- MHA 0 ----
    gemm_kernel<0, 0, 0><<<gBig, 256>>>(E, Wq0, nullptr, bQ, M, DD, DD);
    gemm_kernel<0, 0, 0><<<gBig, 256>>>(E, Wk0, nullptr, bK, M, DD, DD);
    gemm_kernel<0, 0, 0><<<gBig, 256>>>(E, Wv0, nullptr, bV, M, DD, DD);
    attn_kernel<<<gAttn, 256, ATTN_SMEM_BYTES>>>(bQ, bK, bV, bO);
    gemm_kernel<0, 1, 0><<<gBig, 256>>>(bO, Wo0, nullptr, bX, M, DD, DD);  // + gelu

    // ---- MHA 1 ----
    gemm_kernel<0, 0, 0><<<gBig, 256>>>(bX, Wq1, nullptr, bQ, M, DD, DD);
    gemm_kernel<0, 0, 0><<<gBig, 256>>>(bX, Wk1, nullptr, bK, M, DD, DD);
    gemm_kernel<0, 0, 0><<<gBig, 256>>>(bX, Wv1, nullptr, bV, M, DD, DD);
    attn_kernel<<<gAttn, 256, ATTN_SMEM_BYTES>>>(bQ, bK, bV, bO);
    gemm_kernel<0, 0, 0><<<gBig, 256>>>(bO, Wo1, nullptr, bX, M, DD, DD);

    // ---- aggregate path ----
    colmean_gelu_kernel<<<BB, 256>>>(bX, aggrg);
    // aggr_res = aggrg @ res_W + res_b
    gemm_kernel<0, 0, 1><<<gSmall, 256>>>(aggrg, resW, resb, ares, BB, DD, DD);
    // rowbias = gelu(aggr_res) @ ff_W1[:256] + ff_b1
    gemm_kernel<1, 0, 1><<<gSmall, 256>>>(ares, ffW1, ffb1, rbias, BB, DD, DD);
    // h = gelu( gelu(E) @ ff_W1[256:] + rowbias[b] )
    gemm_kernel<1, 1, 2><<<gBig, 256>>>(E, ffW1 + (size_t)DD * DD, rbias, bQ, M, DD, DD);
    // f = h @ ff_W2 + ff_b2
    gemm_kernel<0, 0, 1><<<gBig, 256>>>(bQ, ffW2, ffb2, bK, M, DD, DD);

    // ---- prototypical scoring (S = f f^T folded into class sums) ----
    class_sum_kernel<<<BB, 256>>>(bK, lab, G, CNT);
    proto_out_kernel<<<dim3(NN, BB), 256>>>(bK, G, CNT, lab, out);
}

// round 3
// speedup vs baseline: 1.1926x; 1.1926x over previous
#include <cuda_runtime.h>
#include <cuda_bf16.h>
#include <math.h>

// Shapes: B=16, N=512, D=256, H=8, DK=32, C=16
#define BB 16
#define NN 512
#define DD 256
#define HH 8
#define DKH 32
#define CC 16

__device__ float g_bufQ[BB * NN * DD];
__device__ float g_bufK[BB * NN * DD];
__device__ float g_bufV[BB * NN * DD];
__device__ float g_bufO[BB * NN * DD];
__device__ float g_bufX[BB * NN * DD];
__device__ float g_aggrg[BB * DD];
__device__ float g_ares[BB * DD];
__device__ float g_rbias[BB * DD];
__device__ float g_G[BB * CC * DD];
__device__ float g_CNT[BB * CC];

__device__ __forceinline__ float gelu_f(float x) {
    return 0.5f * x * (1.0f + erff(x * 0.7071067811865475f));
}

// exp(x) on the FMA/ALU pipes (no MUFU). Accurate to ~1.2e-7 rel for x <= 0 range.
__device__ __forceinline__ float fast_exp(float x) {
    float y = x * 1.4426950408889634f;          // log2(e)
    y = fmaxf(y, -126.0f);                      // avoid denormal scale
    float f = rintf(y);
    float z = y - f;                            // [-0.5, 0.5]
    // 2^z Taylor in (ln2*z), degree 6
    float p = 1.5403530393381609e-4f;
    p = fmaf(p, z, 1.3333558146428443e-3f);
    p = fmaf(p, z, 9.6181291076284772e-3f);
    p = fmaf(p, z, 5.5504108664821580e-2f);
    p = fmaf(p, z, 2.4022650695910072e-1f);
    p = fmaf(p, z, 6.9314718055994531e-1f);
    p = fmaf(p, z, 1.0f);
    int e = (int)f;
    float s = __int_as_float((e + 127) << 23);
    return p * s;
}

// ---------------------------------------------------------------------------
// SGEMM: C[M,N] = act_out( act_in(A)[M,K] @ W[K,N] + bias )
// BM=BN=64, BK=16, 128 threads, 8x4 microtile.
// ---------------------------------------------------------------------------
#define BM 64
#define BN 64
#define BK 16

template <int AIN, int AOUT, int BMODE>
__global__ __launch_bounds__(128) void gemm_kernel(
    const float* __restrict__ A, const float* __restrict__ W,
    const float* __restrict__ bias, float* __restrict__ C,
    int M, int N, int K)
{
    __shared__ float As[BK][BM + 4];
    __shared__ float Ws[BK][BN + 4];

    const int bm = blockIdx.x * BM;
    const int bn = blockIdx.y * BN;
    const int t  = threadIdx.x;
    const int tx = t & 15;        // n-group: cols tx*4..tx*4+3
    const int ty = t >> 4;        // m-group: rows ty*8..ty*8+7

    const int a_r = t >> 1;           // 0..63
    const int a_k = (t & 1) * 8;      // 0 or 8
    const int w_k = t >> 3;           // 0..15
    const int w_n = (t & 7) * 8;      // 0..56

    float acc[8][4];
    #pragma unroll
    for (int i = 0; i < 8; i++)
        #pragma unroll
        for (int j = 0; j < 4; j++) acc[i][j] = 0.0f;

    for (int k0 = 0; k0 < K; k0 += BK) {
        // A tile 64x16 -> transposed
        float4 av0 = make_float4(0.f,0.f,0.f,0.f), av1 = make_float4(0.f,0.f,0.f,0.f);
        if (bm + a_r < M) {
            av0 = *(const float4*)&A[(size_t)(bm + a_r) * K + k0 + a_k];
            av1 = *(const float4*)&A[(size_t)(bm + a_r) * K + k0 + a_k + 4];
        }
        if (AIN) {
            av0.x = gelu_f(av0.x); av0.y = gelu_f(av0.y); av0.z = gelu_f(av0.z); av0.w = gelu_f(av0.w);
            av1.x = gelu_f(av1.x); av1.y = gelu_f(av1.y); av1.z = gelu_f(av1.z); av1.w = gelu_f(av1.w);
        }
        As[a_k + 0][a_r] = av0.x; As[a_k + 1][a_r] = av0.y;
        As[a_k + 2][a_r] = av0.z; As[a_k + 3][a_r] = av0.w;
        As[a_k + 4][a_r] = av1.x; As[a_k + 5][a_r] = av1.y;
        As[a_k + 6][a_r] = av1.z; As[a_k + 7][a_r] = av1.w;

        // W tile 16x64
        float4 wv0 = *(const float4*)&W[(size_t)(k0 + w_k) * N + bn + w_n];
        float4 wv1 = *(const float4*)&W[(size_t)(k0 + w_k) * N + bn + w_n + 4];
        *(float4*)&Ws[w_k][w_n]     = wv0;
        *(float4*)&Ws[w_k][w_n + 4] = wv1;

        __syncthreads();

        #pragma unroll
        for (int k = 0; k < BK; k++) {
            float4 a0 = *(const float4*)&As[k][ty * 8];
            float4 a1 = *(const float4*)&As[k][ty * 8 + 4];
            float4 b  = *(const float4*)&Ws[k][tx * 4];
            float ar[8] = {a0.x, a0.y, a0.z, a0.w, a1.x, a1.y, a1.z, a1.w};
            float br[4] = {b.x, b.y, b.z, b.w};
            #pragma unroll
            for (int i = 0; i < 8; i++)
                #pragma unroll
                for (int j = 0; j < 4; j++)
                    acc[i][j] = fmaf(ar[i], br[j], acc[i][j]);
        }
        __syncthreads();
    }

    #pragma unroll
    for (int i = 0; i < 8; i++) {
        int row = bm + ty * 8 + i;
        if (row >= M) continue;
        int col = bn + tx * 4;
        float v0 = acc[i][0], v1 = acc[i][1], v2 = acc[i][2], v3 = acc[i][3];
        if (BMODE == 1) {
            v0 += bias[col]; v1 += bias[col+1]; v2 += bias[col+2]; v3 += bias[col+3];
        }
        if (BMODE == 2) {
            const float* bb = bias + (size_t)(row >> 9) * N + col;
            v0 += bb[0]; v1 += bb[1]; v2 += bb[2]; v3 += bb[3];
        }
        if (AOUT) { v0 = gelu_f(v0); v1 = gelu_f(v1); v2 = gelu_f(v2); v3 = gelu_f(v3); }
        *(float4*)&C[(size_t)row * N + col] = make_float4(v0, v1, v2, v3);
    }
}

// ---------------------------------------------------------------------------
// Fused attention: 64 queries of one (b,h) per block, 256 threads.
// Scores kept in smem (row-major, SP=516). exp via FMA polynomial (no MUFU).
// Whole V head (512x32, padded 36) staged in smem. Softmax normalization folded
// into PV epilogue via row sums.
// ---------------------------------------------------------------------------
#define SP 516
#define ATTN_SMEM_FLOATS (64*33 + 64*33 + 64 + 64*SP + 512*36)
#define ATTN_SMEM_BYTES  (ATTN_SMEM_FLOATS * 4)

__global__ __launch_bounds__(256) void attn_kernel(
    const float* __restrict__ Qp, const float* __restrict__ Kp,
    const float* __restrict__ Vp, float* __restrict__ Op)
{
    extern __shared__ float sm[];
    float* qs = sm;                    // [64][33]
    float* ks = sm + 2112;             // [64][33]
    float* rs = sm + 4224;             // [64] row sums
    float* sc = sm + 4288;             // [64][SP]
    float* vs = sm + 4288 + 64 * SP;   // [512][36]

    const int t  = threadIdx.x;
    const int qb = blockIdx.x * 64;
    const int h  = blockIdx.y;
    const int b  = blockIdx.z;
    const float scale = 0.17677669529663688f;  // 1/sqrt(32)

    const size_t baseQ  = ((size_t)(b * NN + qb)) * DD + h * DKH;
    const size_t baseKV = ((size_t)(b * NN)) * DD + h * DKH;

    // load Q (pre-scaled): 512 float4s
    for (int i = t; i < 512; i += 256) {
        int r = i >> 3, c = (i & 7) * 4;
        float4 q4 = *(const float4*)&Qp[baseQ + (size_t)r * DD + c];
        qs[r * 33 + c + 0] = q4.x * scale;
        qs[r * 33 + c + 1] = q4.y * scale;
        qs[r * 33 + c + 2] = q4.z * scale;
        qs[r * 33 + c + 3] = q4.w * scale;
    }
    // stage whole V head: 4096 float4s (used after later syncs)
    for (int i = t; i < 4096; i += 256) {
        int r = i >> 3, c = (i & 7) * 4;
        float4 v4 = *(const float4*)&Vp[baseKV + (size_t)r * DD + c];
        *(float4*)&vs[r * 36 + c] = v4;
    }

    const int tx = t & 15, ty = t >> 4;

    // ---- scores = Q @ K^T ----
    for (int kt = 0; kt < 8; kt++) {
        const int kb = kt * 64;
        __syncthreads();
        for (int i = t; i < 512; i += 256) {
            int r = i >> 3, c = (i & 7) * 4;
            float4 k4 = *(const float4*)&Kp[baseKV + (size_t)(kb + r) * DD + c];
            ks[r * 33 + c + 0] = k4.x;
            ks[r * 33 + c + 1] = k4.y;
            ks[r * 33 + c + 2] = k4.z;
            ks[r * 33 + c + 3] = k4.w;
        }
        __syncthreads();
        float acc[4][4];
        #pragma unroll
        for (int i = 0; i < 4; i++)
            #pragma unroll
            for (int j = 0; j < 4; j++) acc[i][j] = 0.0f;
        #pragma unroll
        for (int d = 0; d < 32; d++) {
            float a0 = qs[(ty * 4 + 0) * 33 + d];
            float a1 = qs[(ty * 4 + 1) * 33 + d];
            float a2 = qs[(ty * 4 + 2) * 33 + d];
            float a3 = qs[(ty * 4 + 3) * 33 + d];
            float b0 = ks[(tx * 4 + 0) * 33 + d];
            float b1 = ks[(tx * 4 + 1) * 33 + d];
            float b2 = ks[(tx * 4 + 2) * 33 + d];
            float b3 = ks[(tx * 4 + 3) * 33 + d];
            acc[0][0] += a0 * b0; acc[0][1] += a0 * b1; acc[0][2] += a0 * b2; acc[0][3] += a0 * b3;
            acc[1][0] += a1 * b0; acc[1][1] += a1 * b1; acc[1][2] += a1 * b2; acc[1][3] += a1 * b3;
            acc[2][0] += a2 * b0; acc[2][1] += a2 * b1; acc[2][2] += a2 * b2; acc[2][3] += a2 * b3;
            acc[3][0] += a3 * b0; acc[3][1] += a3 * b1; acc[3][2] += a3 * b2; acc[3][3] += a3 * b3;
        }
        #pragma unroll
        for (int i = 0; i < 4; i++)
            #pragma unroll
            for (int j = 0; j < 4; j++)
                sc[(ty * 4 + i) * SP + kb + tx * 4 + j] = acc[i][j];
    }
    __syncthreads();

    // ---- row softmax: max + exp (FMA poly) + running sum; normalize deferred ----
    {
        const int w = t >> 5, lane = t & 31;
        for (int r = w * 8; r < w * 8 + 8; r++) {
            float mx = -1e30f;
            for (int i = lane; i < 512; i += 32) mx = fmaxf(mx, sc[r * SP + i]);
            #pragma unroll
            for (int o = 16; o; o >>= 1) mx = fmaxf(mx, __shfl_xor_sync(0xFFFFFFFFu, mx, o));
            float s = 0.0f;
            for (int i = lane; i < 512; i += 32) {
                float e = fast_exp(sc[r * SP + i] - mx);
                sc[r * SP + i] = e;
                s += e;
            }
            #pragma unroll
            for (int o = 16; o; o >>= 1) s += __shfl_xor_sync(0xFFFFFFFFu, s, o);
            if (lane == 0) rs[r] = s;
        }
    }
    __syncthreads();

    // ---- O = P @ V (128 threads, 4q x 4d microtile, float4 P & V) ----
    if (t < 128) {
        const int qg = t >> 3;          // 0..15 -> queries qg*4..qg*4+3
        const int dg = (t & 7) * 4;     // 0,4,...,28
        float o0[4] = {0,0,0,0}, o1[4] = {0,0,0,0}, o2[4] = {0,0,0,0}, o3[4] = {0,0,0,0};
        const float* p0 = sc + (qg * 4 + 0) * SP;
        const float* p1 = sc + (qg * 4 + 1) * SP;
        const float* p2 = sc + (qg * 4 + 2) * SP;
        const float* p3 = sc + (qg * 4 + 3) * SP;
        for (int kk = 0; kk < 512; kk += 4) {
            float4 P0 = *(const float4*)&p0[kk];
            float4 P1 = *(const float4*)&p1[kk];
            float4 P2 = *(const float4*)&p2[kk];
            float4 P3 = *(const float4*)&p3[kk];
            {
                float4 v = *(const float4*)&vs[(kk + 0) * 36 + dg];
                o0[0]=fmaf(P0.x,v.x,o0[0]); o0[1]=fmaf(P0.x,v.y,o0[1]); o0[2]=fmaf(P0.x,v.z,o0[2]); o0[3]=fmaf(P0.x,v.w,o0[3]);
                o1[0]=fmaf(P1.x,v.x,o1[0]); o1[1]=fmaf(P1.x,v.y,o1[1]); o1[2]=fmaf(P1.x,v.z,o1[2]); o1[3]=fmaf(P1.x,v.w,o1[3]);
                o2[0]=fmaf(P2.x,v.x,o2[0]); o2[1]=fmaf(P2.x,v.y,o2[1]); o2[2]=fmaf(P2.x,v.z,o2[2]); o2[3]=fmaf(P2.x,v.w,o2[3]);
                o3[0]=fmaf(P3.x,v.x,o3[0]); o3[1]=fmaf(P3.x,v.y,o3[1]); o3[2]=fmaf(P3.x,v.z,o3[2]); o3[3]=fmaf(P3.x,v.w,o3[3]);
            }
            {
                float4 v = *(const float4*)&vs[(kk + 1) * 36 + dg];
                o0[0]=fmaf(P0.y,v.x,o0[0]); o0[1]=fmaf(P0.y,v.y,o0[1]); o0[2]=fmaf(P0.y,v.z,o0[2]); o0[3]=fmaf(P0.y,v.w,o0[3]);
                o1[0]=fmaf(P1.y,v.x,o1[0]); o1[1]=fmaf(P1.y,v.y,o1[1]); o1[2]=fmaf(P1.y,v.z,o1[2]); o1[3]=fmaf(P1.y,v.w,o1[3]);
                o2[0]=fmaf(P2.y,v.x,o2[0]); o2[1]=fmaf(P2.y,v.y,o2[1]); o2[2]=fmaf(P2.y,v.z,o2[2]); o2[3]=fmaf(P2.y,v.w,o2[3]);
                o3[0]=fmaf(P3.y,v.x,o3[0]); o3[1]=fmaf(P3.y,v.y,o3[1]); o3[2]=fmaf(P3.y,v.z,o3[2]); o3[3]=fmaf(P3.y,v.w,o3[3]);
            }
            {
                float4 v = *(const float4*)&vs[(kk + 2) * 36 + dg];
                o0[0]=fmaf(P0.z,v.x,o0[0]); o0[1]=fmaf(P0.z,v.y,o0[1]); o0[2]=fmaf(P0.z,v.z,o0[2]); o0[3]=fmaf(P0.z,v.w,o0[3]);
                o1[0]=fmaf(P1.z,v.x,o1[0]); o1[1]=fmaf(P1.z,v.y,o1[1]); o1[2]=fmaf(P1.z,v.z,o1[2]); o1[3]=fmaf(P1.z,v.w,o1[3]);
                o2[0]=fmaf(P2.z,v.x,o2[0]); o2[1]=fmaf(P2.z,v.y,o2[1]); o2[2]=fmaf(P2.z,v.z,o2[2]); o2[3]=fmaf(P2.z,v.w,o2[3]);
                o3[0]=fmaf(P3.z,v.x,o3[0]); o3[1]=fmaf(P3.z,v.y,o3[1]); o3[2]=fmaf(P3.z,v.z,o3[2]); o3[3]=fmaf(P3.z,v.w,o3[3]);
            }
            {
                float4 v = *(const float4*)&vs[(kk + 3) * 36 + dg];
                o0[0]=fmaf(P0.w,v.x,o0[0]); o0[1]=fmaf(P0.w,v.y,o0[1]); o0[2]=fmaf(P0.w,v.z,o0[2]); o0[3]=fmaf(P0.w,v.w,o0[3]);
                o1[0]=fmaf(P1.w,v.x,o1[0]); o1[1]=fmaf(P1.w,v.y,o1[1]); o1[2]=fmaf(P1.w,v.z,o1[2]); o1[3]=fmaf(P1.w,v.w,o1[3]);
                o2[0]=fmaf(P2.w,v.x,o2[0]); o2[1]=fmaf(P2.w,v.y,o2[1]); o2[2]=fmaf(P2.w,v.z,o2[2]); o2[3]=fmaf(P2.w,v.w,o2[3]);
                o3[0]=fmaf(P3.w,v.x,o3[0]); o3[1]=fmaf(P3.w,v.y,o3[1]); o3[2]=fmaf(P3.w,v.z,o3[2]); o3[3]=fmaf(P3.w,v.w,o3[3]);
            }
        }
        float i0 = 1.0f / rs[qg * 4 + 0];
        float i1 = 1.0f / rs[qg * 4 + 1];
        float i2 = 1.0f / rs[qg * 4 + 2];
        float i3 = 1.0f / rs[qg * 4 + 3];
        *(float4*)&Op[baseQ + (size_t)(qg * 4 + 0) * DD + dg] = make_float4(o0[0]*i0, o0[1]*i0, o0[2]*i0, o0[3]*i0);
        *(float4*)&Op[baseQ + (size_t)(qg * 4 + 1) * DD + dg] = make_float4(o1[0]*i1, o1[1]*i1, o1[2]*i1, o1[3]*i1);
        *(float4*)&Op[baseQ + (size_t)(qg * 4 + 2) * DD + dg] = make_float4(o2[0]*i2, o2[1]*i2, o2[2]*i2, o2[3]*i2);
        *(float4*)&Op[baseQ + (size_t)(qg * 4 + 3) * DD + dg] = make_float4(o3[0]*i3, o3[1]*i3, o3[2]*i3, o3[3]*i3);
    }
}

// ---------------------------------------------------------------------------
__global__ __launch_bounds__(256) void colmean_gelu_kernel(
    const float* __restrict__ X, float* __restrict__ out)
{
    const int b = blockIdx.x;
    const int d = threadIdx.x;
    float s = 0.0f;
    const float* base = X + (size_t)b * NN * DD + d;
    for (int n = 0; n < NN; n++) s += base[(size_t)n * DD];
    out[b * DD + d] = gelu_f(s * (1.0f / (float)NN));
}

__global__ __launch_bounds__(256) void class_sum_kernel(
    const float* __restrict__ F, const int* __restrict__ lab,
    float* __restrict__ G, float* __restrict__ CNT)
{
    __shared__ float gs[CC * DD];
    __shared__ float cs[CC];
    const int b = blockIdx.x;
    const int t = threadIdx.x;
    for (int i = t; i < CC * DD; i += 256) gs[i] = 0.0f;
    if (t < CC) cs[t] = 0.0f;
    __syncthreads();
    for (int n = 0; n < NN; n++) {
        int c = lab[b * NN + n];
        gs[c * DD + t] += F[((size_t)b * NN + n) * DD + t];
        if (t == 0) cs[c] += 1.0f;
    }
    __syncthreads();
    for (int i = t; i < CC * DD; i += 256) G[(size_t)b * CC * DD + i] = gs[i];
    if (t < CC) CNT[b * CC + t] = cs[t];
}

__global__ __launch_bounds__(256) void proto_out_kernel(
    const float* __restrict__ F, const float* __restrict__ G,
    const float* __restrict__ CNT, const int* __restrict__ lab,
    float* __restrict__ out)
{
    __shared__ float fs[DD];
    const int n = blockIdx.x;
    const int b = blockIdx.y;
    const int t = threadIdx.x;
    fs[t] = F[((size_t)b * NN + n) * DD + t];
    __syncthreads();

    const int w = t >> 5, lane = t & 31;
    float sd = 0.0f;
    for (int i = lane; i < DD; i += 32) sd += fs[i] * fs[i];
    #pragma unroll
    for (int o = 16; o; o >>= 1) sd += __shfl_xor_sync(0xFFFFFFFFu, sd, o);

    const int labn = lab[b * NN + n];
    #pragma unroll
    for (int cc = 0; cc < 2; cc++) {
        const int c = w * 2 + cc;
        const float* g = G + (size_t)b * CC * DD + c * DD;
        float dp = 0.0f;
        for (int i = lane; i < DD; i += 32) dp += fs[i] * g[i];
        #pragma unroll
        for (int o = 16; o; o >>= 1) dp += __shfl_xor_sync(0xFFFFFFFFu, dp, o);
        if (lane == 0) {
            float same = (labn == c) ? 1.0f : 0.0f;
            out[((size_t)b * NN + n) * CC + c] =
                (dp - same * sd) / (CNT[b * CC + c] - same);
        }
    }
}

// ---------------------------------------------------------------------------
extern "C" void kernel_launch(void* const* d_in, const int* in_sizes, int n_in,
                              void* d_out, int out_size)
{
    const float* E    = (const float*)d_in[0];
    const int*   lab  = (const int*)  d_in[1];
    const float* Wq0  = (const float*)d_in[2];
    const float* Wk0  = (const float*)d_in[3];
    const float* Wv0  = (const float*)d_in[4];
    const float* Wo0  = (const float*)d_in[5];
    const float* Wq1  = (const float*)d_in[6];
    const float* Wk1  = (const float*)d_in[7];
    const float* Wv1  = (const float*)d_in[8];
    const float* Wo1  = (const float*)d_in[9];
    const float* resW = (const float*)d_in[10];
    const float* resb = (const float*)d_in[11];
    const float* ffW1 = (const float*)d_in[12];
    const float* ffb1 = (const float*)d_in[13];
    const float* ffW2 = (const float*)d_in[14];
    const float* ffb2 = (const float*)d_in[15];
    float* out = (float*)d_out;

    float *bQ, *bK, *bV, *bO, *bX, *aggrg, *ares, *rbias, *G, *CNT;
    cudaGetSymbolAddress((void**)&bQ,    g_bufQ);
    cudaGetSymbolAddress((void**)&bK,    g_bufK);
    cudaGetSymbolAddress((void**)&bV,    g_bufV);
    cudaGetSymbolAddress((void**)&bO,    g_bufO);
    cudaGetSymbolAddress((void**)&bX,    g_bufX);
    cudaGetSymbolAddress((void**)&aggrg, g_aggrg);
    cudaGetSymbolAddress((void**)&ares,  g_ares);
    cudaGetSymbolAddress((void**)&rbias, g_rbias);
    cudaGetSymbolAddress((void**)&G,     g_G);
    cudaGetSymbolAddress((void**)&CNT,   g_CNT);

    cudaFuncSetAttribute(attn_kernel,
                         cudaFuncAttributeMaxDynamicSharedMemorySize,
                         ATTN_SMEM_BYTES);

    const int M = BB * NN;                 // 8192
    dim3 gBig(M / BM, DD / BN);            // (128, 4)
    dim3 gSmall(1, DD / BN);               // (1, 4)
    dim3 gAttn(NN / 64, HH, BB);           // (8, 8, 16)

    // ---- MHA 0 ----
    gemm_kernel<0, 0, 0><<<gBig, 128>>>(E, Wq0, nullptr, bQ, M, DD, DD);
    gemm_kernel<0, 0, 0><<<gBig, 128>>>(E, Wk0, nullptr, bK, M, DD, DD);
    gemm_kernel<0, 0, 0><<<gBig, 128>>>(E, Wv0, nullptr, bV, M, DD, DD);
    attn_kernel<<<gAttn, 256, ATTN_SMEM_BYTES>>>(bQ, bK, bV, bO);
    gemm_kernel<0, 1, 0><<<gBig, 128>>>(bO, Wo0, nullptr, bX, M, DD, DD);  // + gelu

    // ---- MHA 1 ----
    gemm_kernel<0, 0, 0><<<gBig, 128>>>(bX, Wq1, nullptr, bQ, M, DD, DD);
    gemm_kernel<0, 0, 0><<<gBig, 128>>>(bX, Wk1, nullptr, bK, M, DD, DD);
    gemm_kernel<0, 0, 0><<<gBig, 128>>>(bX, Wv1, nullptr, bV, M, DD, DD);
    attn_kernel<<<gAttn, 256, ATTN_SMEM_BYTES>>>(bQ, bK, bV, bO);
    gemm_kernel<0, 0, 0><<<gBig, 128>>>(bO, Wo1, nullptr, bX, M, DD, DD);

    // ---- aggregate path ----
    colmean_gelu_kernel<<<BB, 256>>>(bX, aggrg);
    gemm_kernel<0, 0, 1><<<gSmall, 128>>>(aggrg, resW, resb, ares, BB, DD, DD);
    gemm_kernel<1, 0, 1><<<gSmall, 128>>>(ares, ffW1, ffb1, rbias, BB, DD, DD);
    gemm_kernel<1, 1, 2><<<gBig, 128>>>(E, ffW1 + (size_t)DD * DD, rbias, bQ, M, DD, DD);
    gemm_kernel<0, 0, 1><<<gBig, 128>>>(bQ, ffW2, ffb2, bK, M, DD, DD);

    // ---- prototypical scoring ----
    class_sum_kernel<<<BB, 256>>>(bK, lab, G, CNT);
    proto_out_kernel<<<dim3(NN, BB), 256>>>(bK, G, CNT, lab, out);
}

// round 4
// speedup vs baseline: 1.2587x; 1.0554x over previous
#include <cuda_runtime.h>
#include <cuda_bf16.h>
#include <math.h>

// Shapes: B=16, N=512, D=256, H=8, DK=32, C=16
#define BB 16
#define NN 512
#define DD 256
#define HH 8
#define DKH 32
#define CC 16

__device__ float g_bufQ[BB * NN * DD];
__device__ float g_bufK[BB * NN * DD];
__device__ float g_bufV[BB * NN * DD];
__device__ float g_bufO[BB * NN * DD];
__device__ float g_bufX[BB * NN * DD];
__device__ float g_aggrg[BB * DD];
__device__ float g_ares[BB * DD];
__device__ float g_rbias[BB * DD];
__device__ float g_G[BB * CC * DD];
__device__ float g_CNT[BB * CC];

__device__ __forceinline__ float gelu_f(float x) {
    return 0.5f * x * (1.0f + erff(x * 0.7071067811865475f));
}

// exp(x) on the FMA/ALU pipes (no MUFU). ~1.2e-7 rel error.
__device__ __forceinline__ float fast_exp(float x) {
    float y = x * 1.4426950408889634f;
    y = fmaxf(y, -126.0f);
    float f = rintf(y);
    float z = y - f;
    float p = 1.5403530393381609e-4f;
    p = fmaf(p, z, 1.3333558146428443e-3f);
    p = fmaf(p, z, 9.6181291076284772e-3f);
    p = fmaf(p, z, 5.5504108664821580e-2f);
    p = fmaf(p, z, 2.4022650695910072e-1f);
    p = fmaf(p, z, 6.9314718055994531e-1f);
    p = fmaf(p, z, 1.0f);
    int e = (int)f;
    float s = __int_as_float((e + 127) << 23);
    return p * s;
}

// ---------------------------------------------------------------------------
// SGEMM (unchanged from R3): BM=BN=64, BK=16, 128 threads, 8x4 microtile.
// ---------------------------------------------------------------------------
#define BM 64
#define BN 64
#define BK 16

template <int AIN, int AOUT, int BMODE>
__global__ __launch_bounds__(128) void gemm_kernel(
    const float* __restrict__ A, const float* __restrict__ W,
    const float* __restrict__ bias, float* __restrict__ C,
    int M, int N, int K)
{
    __shared__ float As[BK][BM + 4];
    __shared__ float Ws[BK][BN + 4];

    const int bm = blockIdx.x * BM;
    const int bn = blockIdx.y * BN;
    const int t  = threadIdx.x;
    const int tx = t & 15;
    const int ty = t >> 4;

    const int a_r = t >> 1;
    const int a_k = (t & 1) * 8;
    const int w_k = t >> 3;
    const int w_n = (t & 7) * 8;

    float acc[8][4];
    #pragma unroll
    for (int i = 0; i < 8; i++)
        #pragma unroll
        for (int j = 0; j < 4; j++) acc[i][j] = 0.0f;

    for (int k0 = 0; k0 < K; k0 += BK) {
        float4 av0 = make_float4(0.f,0.f,0.f,0.f), av1 = make_float4(0.f,0.f,0.f,0.f);
        if (bm + a_r < M) {
            av0 = *(const float4*)&A[(size_t)(bm + a_r) * K + k0 + a_k];
            av1 = *(const float4*)&A[(size_t)(bm + a_r) * K + k0 + a_k + 4];
        }
        if (AIN) {
            av0.x = gelu_f(av0.x); av0.y = gelu_f(av0.y); av0.z = gelu_f(av0.z); av0.w = gelu_f(av0.w);
            av1.x = gelu_f(av1.x); av1.y = gelu_f(av1.y); av1.z = gelu_f(av1.z); av1.w = gelu_f(av1.w);
        }
        As[a_k + 0][a_r] = av0.x; As[a_k + 1][a_r] = av0.y;
        As[a_k + 2][a_r] = av0.z; As[a_k + 3][a_r] = av0.w;
        As[a_k + 4][a_r] = av1.x; As[a_k + 5][a_r] = av1.y;
        As[a_k + 6][a_r] = av1.z; As[a_k + 7][a_r] = av1.w;

        float4 wv0 = *(const float4*)&W[(size_t)(k0 + w_k) * N + bn + w_n];
        float4 wv1 = *(const float4*)&W[(size_t)(k0 + w_k) * N + bn + w_n + 4];
        *(float4*)&Ws[w_k][w_n]     = wv0;
        *(float4*)&Ws[w_k][w_n + 4] = wv1;

        __syncthreads();

        #pragma unroll
        for (int k = 0; k < BK; k++) {
            float4 a0 = *(const float4*)&As[k][ty * 8];
            float4 a1 = *(const float4*)&As[k][ty * 8 + 4];
            float4 b  = *(const float4*)&Ws[k][tx * 4];
            float ar[8] = {a0.x, a0.y, a0.z, a0.w, a1.x, a1.y, a1.z, a1.w};
            float br[4] = {b.x, b.y, b.z, b.w};
            #pragma unroll
            for (int i = 0; i < 8; i++)
                #pragma unroll
                for (int j = 0; j < 4; j++)
                    acc[i][j] = fmaf(ar[i], br[j], acc[i][j]);
        }
        __syncthreads();
    }

    #pragma unroll
    for (int i = 0; i < 8; i++) {
        int row = bm + ty * 8 + i;
        if (row >= M) continue;
        int col = bn + tx * 4;
        float v0 = acc[i][0], v1 = acc[i][1], v2 = acc[i][2], v3 = acc[i][3];
        if (BMODE == 1) {
            v0 += bias[col]; v1 += bias[col+1]; v2 += bias[col+2]; v3 += bias[col+3];
        }
        if (BMODE == 2) {
            const float* bb = bias + (size_t)(row >> 9) * N + col;
            v0 += bb[0]; v1 += bb[1]; v2 += bb[2]; v3 += bb[3];
        }
        if (AOUT) { v0 = gelu_f(v0); v1 = gelu_f(v1); v2 = gelu_f(v2); v3 = gelu_f(v3); }
        *(float4*)&C[(size_t)row * N + col] = make_float4(v0, v1, v2, v3);
    }
}

// ---------------------------------------------------------------------------
// Fused attention v3: 64 queries per block, 256 threads.
// QK: transposed Q/K smem (k-major), 8q x 4k microtile over 128-key tiles
//     -> A loads warp-broadcast, 3 LDS.128 per 32 FMA.
// Softmax: poly exp, deferred normalization (row sums).
// PV: all 256 threads, 2q x 4d, V staged per 128-key tile.
// smem layout (floats):
//   qs [32][68]   (d-major Q, prescaled)            @0      2176
//   ks [32][132]  (d-major K tile, 128 keys)        @2176   4224
//   vs [128][36]  (row-major V tile)                @6400   4608
//   rs [64]                                          @11008  64
//   sc [64][516]                                     @11072  33024
// total 44096 floats = 172.25 KB
// ---------------------------------------------------------------------------
#define SP 516
#define ATTN_SMEM_FLOATS 44096
#define ATTN_SMEM_BYTES  (ATTN_SMEM_FLOATS * 4)

__global__ __launch_bounds__(256) void attn_kernel(
    const float* __restrict__ Qp, const float* __restrict__ Kp,
    const float* __restrict__ Vp, float* __restrict__ Op)
{
    extern __shared__ float sm[];
    float* qs = sm;            // [32][68]
    float* ks = sm + 2176;     // [32][132]
    float* vs = sm + 6400;     // [128][36]
    float* rs = sm + 11008;    // [64]
    float* sc = sm + 11072;    // [64][516]

    const int t  = threadIdx.x;
    const int qb = blockIdx.x * 64;
    const int h  = blockIdx.y;
    const int b  = blockIdx.z;
    const float scale = 0.17677669529663688f;  // 1/sqrt(32)

    const size_t baseQ  = ((size_t)(b * NN + qb)) * DD + h * DKH;
    const size_t baseKV = ((size_t)(b * NN)) * DD + h * DKH;

    // load Q transposed (d-major), prescaled: 64 rows x 32 d
    for (int i = t; i < 512; i += 256) {
        int r = i >> 3, c = (i & 7) * 4;
        float4 q4 = *(const float4*)&Qp[baseQ + (size_t)r * DD + c];
        qs[(c + 0) * 68 + r] = q4.x * scale;
        qs[(c + 1) * 68 + r] = q4.y * scale;
        qs[(c + 2) * 68 + r] = q4.z * scale;
        qs[(c + 3) * 68 + r] = q4.w * scale;
    }

    const int ty = t >> 5;   // 0..7  -> q rows ty*8 .. ty*8+7
    const int tx = t & 31;   // 0..31 -> k cols tx*4 .. tx*4+3

    // ---- scores = Q @ K^T over 4 key-tiles of 128 ----
    for (int kt = 0; kt < 4; kt++) {
        const int kb = kt * 128;
        __syncthreads();
        // stage K tile transposed (d-major): 128 rows x 32 d
        for (int i = t; i < 1024; i += 256) {
            int r = i >> 3, c = (i & 7) * 4;
            float4 k4 = *(const float4*)&Kp[baseKV + (size_t)(kb + r) * DD + c];
            ks[(c + 0) * 132 + r] = k4.x;
            ks[(c + 1) * 132 + r] = k4.y;
            ks[(c + 2) * 132 + r] = k4.z;
            ks[(c + 3) * 132 + r] = k4.w;
        }
        __syncthreads();

        float acc[8][4];
        #pragma unroll
        for (int i = 0; i < 8; i++)
            #pragma unroll
            for (int j = 0; j < 4; j++) acc[i][j] = 0.0f;

        #pragma unroll
        for (int d = 0; d < 32; d++) {
            float4 a0 = *(const float4*)&qs[d * 68 + ty * 8];       // warp-broadcast
            float4 a1 = *(const float4*)&qs[d * 68 + ty * 8 + 4];
            float4 bk = *(const float4*)&ks[d * 132 + tx * 4];
            float ar[8] = {a0.x, a0.y, a0.z, a0.w, a1.x, a1.y, a1.z, a1.w};
            #pragma unroll
            for (int i = 0; i < 8; i++) {
                acc[i][0] = fmaf(ar[i], bk.x, acc[i][0]);
                acc[i][1] = fmaf(ar[i], bk.y, acc[i][1]);
                acc[i][2] = fmaf(ar[i], bk.z, acc[i][2]);
                acc[i][3] = fmaf(ar[i], bk.w, acc[i][3]);
            }
        }
        #pragma unroll
        for (int i = 0; i < 8; i++)
            *(float4*)&sc[(ty * 8 + i) * SP + kb + tx * 4] =
                make_float4(acc[i][0], acc[i][1], acc[i][2], acc[i][3]);
    }
    __syncthreads();

    // ---- row softmax: max + exp (FMA poly) + sums; normalize deferred ----
    {
        const int w = t >> 5, lane = t & 31;
        for (int r = w * 8; r < w * 8 + 8; r++) {
            float mx = -1e30f;
            for (int i = lane; i < 512; i += 32) mx = fmaxf(mx, sc[r * SP + i]);
            #pragma unroll
            for (int o = 16; o; o >>= 1) mx = fmaxf(mx, __shfl_xor_sync(0xFFFFFFFFu, mx, o));
            float s = 0.0f;
            for (int i = lane; i < 512; i += 32) {
                float e = fast_exp(sc[r * SP + i] - mx);
                sc[r * SP + i] = e;
                s += e;
            }
            #pragma unroll
            for (int o = 16; o; o >>= 1) s += __shfl_xor_sync(0xFFFFFFFFu, s, o);
            if (lane == 0) rs[r] = s;
        }
    }

    // ---- O = P @ V, all 256 threads: 2q x 4d each, V staged per 128-tile ----
    const int qg = t >> 3;          // 0..31 -> q rows qg*2, qg*2+1
    const int dg = (t & 7) * 4;     // 0,4,...,28
    float o0[4] = {0,0,0,0}, o1[4] = {0,0,0,0};

    for (int kt = 0; kt < 4; kt++) {
        const int kb = kt * 128;
        __syncthreads();   // vs reuse barrier (also covers softmax completion on kt=0)
        for (int i = t; i < 1024; i += 256) {
            int r = i >> 3, c = (i & 7) * 4;
            float4 v4 = *(const float4*)&Vp[baseKV + (size_t)(kb + r) * DD + c];
            *(float4*)&vs[r * 36 + c] = v4;
        }
        __syncthreads();

        const float* p0 = sc + (size_t)(qg * 2 + 0) * SP + kb;
        const float* p1 = sc + (size_t)(qg * 2 + 1) * SP + kb;
        #pragma unroll 4
        for (int kk = 0; kk < 128; kk += 4) {
            float4 P0 = *(const float4*)&p0[kk];
            float4 P1 = *(const float4*)&p1[kk];
            float4 v;
            v = *(const float4*)&vs[(kk + 0) * 36 + dg];
            o0[0]=fmaf(P0.x,v.x,o0[0]); o0[1]=fmaf(P0.x,v.y,o0[1]); o0[2]=fmaf(P0.x,v.z,o0[2]); o0[3]=fmaf(P0.x,v.w,o0[3]);
            o1[0]=fmaf(P1.x,v.x,o1[0]); o1[1]=fmaf(P1.x,v.y,o1[1]); o1[2]=fmaf(P1.x,v.z,o1[2]); o1[3]=fmaf(P1.x,v.w,o1[3]);
            v = *(const float4*)&vs[(kk + 1) * 36 + dg];
            o0[0]=fmaf(P0.y,v.x,o0[0]); o0[1]=fmaf(P0.y,v.y,o0[1]); o0[2]=fmaf(P0.y,v.z,o0[2]); o0[3]=fmaf(P0.y,v.w,o0[3]);
            o1[0]=fmaf(P1.y,v.x,o1[0]); o1[1]=fmaf(P1.y,v.y,o1[1]); o1[2]=fmaf(P1.y,v.z,o1[2]); o1[3]=fmaf(P1.y,v.w,o1[3]);
            v = *(const float4*)&vs[(kk + 2) * 36 + dg];
            o0[0]=fmaf(P0.z,v.x,o0[0]); o0[1]=fmaf(P0.z,v.y,o0[1]); o0[2]=fmaf(P0.z,v.z,o0[2]); o0[3]=fmaf(P0.z,v.w,o0[3]);
            o1[0]=fmaf(P1.z,v.x,o1[0]); o1[1]=fmaf(P1.z,v.y,o1[1]); o1[2]=fmaf(P1.z,v.z,o1[2]); o1[3]=fmaf(P1.z,v.w,o1[3]);
            v = *(const float4*)&vs[(kk + 3) * 36 + dg];
            o0[0]=fmaf(P0.w,v.x,o0[0]); o0[1]=fmaf(P0.w,v.y,o0[1]); o0[2]=fmaf(P0.w,v.z,o0[2]); o0[3]=fmaf(P0.w,v.w,o0[3]);
            o1[0]=fmaf(P1.w,v.x,o1[0]); o1[1]=fmaf(P1.w,v.y,o1[1]); o1[2]=fmaf(P1.w,v.z,o1[2]); o1[3]=fmaf(P1.w,v.w,o1[3]);
        }
    }
    float i0 = 1.0f / rs[qg * 2 + 0];
    float i1 = 1.0f / rs[qg * 2 + 1];
    *(float4*)&Op[baseQ + (size_t)(qg * 2 + 0) * DD + dg] = make_float4(o0[0]*i0, o0[1]*i0, o0[2]*i0, o0[3]*i0);
    *(float4*)&Op[baseQ + (size_t)(qg * 2 + 1) * DD + dg] = make_float4(o1[0]*i1, o1[1]*i1, o1[2]*i1, o1[3]*i1);
}

// ---------------------------------------------------------------------------
__global__ __launch_bounds__(256) void colmean_gelu_kernel(
    const float* __restrict__ X, float* __restrict__ out)
{
    const int b = blockIdx.x;
    const int d = threadIdx.x;
    float s = 0.0f;
    const float* base = X + (size_t)b * NN * DD + d;
    for (int n = 0; n < NN; n++) s += base[(size_t)n * DD];
    out[b * DD + d] = gelu_f(s * (1.0f / (float)NN));
}

__global__ __launch_bounds__(256) void class_sum_kernel(
    const float* __restrict__ F, const int* __restrict__ lab,
    float* __restrict__ G, float* __restrict__ CNT)
{
    __shared__ float gs[CC * DD];
    __shared__ float cs[CC];
    const int b = blockIdx.x;
    const int t = threadIdx.x;
    for (int i = t; i < CC * DD; i += 256) gs[i] = 0.0f;
    if (t < CC) cs[t] = 0.0f;
    __syncthreads();
    for (int n = 0; n < NN; n++) {
        int c = lab[b * NN + n];
        gs[c * DD + t] += F[((size_t)b * NN + n) * DD + t];
        if (t == 0) cs[c] += 1.0f;
    }
    __syncthreads();
    for (int i = t; i < CC * DD; i += 256) G[(size_t)b * CC * DD + i] = gs[i];
    if (t < CC) CNT[b * CC + t] = cs[t];
}

__global__ __launch_bounds__(256) void proto_out_kernel(
    const float* __restrict__ F, const float* __restrict__ G,
    const float* __restrict__ CNT, const int* __restrict__ lab,
    float* __restrict__ out)
{
    __shared__ float fs[DD];
    const int n = blockIdx.x;
    const int b = blockIdx.y;
    const int t = threadIdx.x;
    fs[t] = F[((size_t)b * NN + n) * DD + t];
    __syncthreads();

    const int w = t >> 5, lane = t & 31;
    float sd = 0.0f;
    for (int i = lane; i < DD; i += 32) sd += fs[i] * fs[i];
    #pragma unroll
    for (int o = 16; o; o >>= 1) sd += __shfl_xor_sync(0xFFFFFFFFu, sd, o);

    const int labn = lab[b * NN + n];
    #pragma unroll
    for (int cc = 0; cc < 2; cc++) {
        const int c = w * 2 + cc;
        const float* g = G + (size_t)b * CC * DD + c * DD;
        float dp = 0.0f;
        for (int i = lane; i < DD; i += 32) dp += fs[i] * g[i];
        #pragma unroll
        for (int o = 16; o; o >>= 1) dp += __shfl_xor_sync(0xFFFFFFFFu, dp, o);
        if (lane == 0) {
            float same = (labn == c) ? 1.0f : 0.0f;
            out[((size_t)b * NN + n) * CC + c] =
                (dp - same * sd) / (CNT[b * CC + c] - same);
        }
    }
}

// ---------------------------------------------------------------------------
extern "C" void kernel_launch(void* const* d_in, const int* in_sizes, int n_in,
                              void* d_out, int out_size)
{
    const float* E    = (const float*)d_in[0];
    const int*   lab  = (const int*)  d_in[1];
    const float* Wq0  = (const float*)d_in[2];
    const float* Wk0  = (const float*)d_in[3];
    const float* Wv0  = (const float*)d_in[4];
    const float* Wo0  = (const float*)d_in[5];
    const float* Wq1  = (const float*)d_in[6];
    const float* Wk1  = (const float*)d_in[7];
    const float* Wv1  = (const float*)d_in[8];
    const float* Wo1  = (const float*)d_in[9];
    const float* resW = (const float*)d_in[10];
    const float* resb = (const float*)d_in[11];
    const float* ffW1 = (const float*)d_in[12];
    const float* ffb1 = (const float*)d_in[13];
    const float* ffW2 = (const float*)d_in[14];
    const float* ffb2 = (const float*)d_in[15];
    float* out = (float*)d_out;

    float *bQ, *bK, *bV, *bO, *bX, *aggrg, *ares, *rbias, *G, *CNT;
    cudaGetSymbolAddress((void**)&bQ,    g_bufQ);
    cudaGetSymbolAddress((void**)&bK,    g_bufK);
    cudaGetSymbolAddress((void**)&bV,    g_bufV);
    cudaGetSymbolAddress((void**)&bO,    g_bufO);
    cudaGetSymbolAddress((void**)&bX,    g_bufX);
    cudaGetSymbolAddress((void**)&aggrg, g_aggrg);
    cudaGetSymbolAddress((void**)&ares,  g_ares);
    cudaGetSymbolAddress((void**)&rbias, g_rbias);
    cudaGetSymbolAddress((void**)&G,     g_G);
    cudaGetSymbolAddress((void**)&CNT,   g_CNT);

    cudaFuncSetAttribute(attn_kernel,
                         cudaFuncAttributeMaxDynamicSharedMemorySize,
                         ATTN_SMEM_BYTES);

    const int M = BB * NN;                 // 8192
    dim3 gBig(M / BM, DD / BN);            // (128, 4)
    dim3 gSmall(1, DD / BN);               // (1, 4)
    dim3 gAttn(NN / 64, HH, BB);           // (8, 8, 16)

    // ---- MHA 0 ----
    gemm_kernel<0, 0, 0><<<gBig, 128>>>(E, Wq0, nullptr, bQ, M, DD, DD);
    gemm_kernel<0, 0, 0><<<gBig, 128>>>(E, Wk0, nullptr, bK, M, DD, DD);
    gemm_kernel<0, 0, 0><<<gBig, 128>>>(E, Wv0, nullptr, bV, M, DD, DD);
    attn_kernel<<<gAttn, 256, ATTN_SMEM_BYTES>>>(bQ, bK, bV, bO);
    gemm_kernel<0, 1, 0><<<gBig, 128>>>(bO, Wo0, nullptr, bX, M, DD, DD);  // + gelu

    // ---- MHA 1 ----
    gemm_kernel<0, 0, 0><<<gBig, 128>>>(bX, Wq1, nullptr, bQ, M, DD, DD);
    gemm_kernel<0, 0, 0><<<gBig, 128>>>(bX, Wk1, nullptr, bK, M, DD, DD);
    gemm_kernel<0, 0, 0><<<gBig, 128>>>(bX, Wv1, nullptr, bV, M, DD, DD);
    attn_kernel<<<gAttn, 256, ATTN_SMEM_BYTES>>>(bQ, bK, bV, bO);
    gemm_kernel<0, 0, 0><<<gBig, 128>>>(bO, Wo1, nullptr, bX, M, DD, DD);

    // ---- aggregate path ----
    colmean_gelu_kernel<<<BB, 256>>>(bX, aggrg);
    gemm_kernel<0, 0, 1><<<gSmall, 128>>>(aggrg, resW, resb, ares, BB, DD, DD);
    gemm_kernel<1, 0, 1><<<gSmall, 128>>>(ares, ffW1, ffb1, rbias, BB, DD, DD);
    gemm_kernel<1, 1, 2><<<gBig, 128>>>(E, ffW1 + (size_t)DD * DD, rbias, bQ, M, DD, DD);
    gemm_kernel<0, 0, 1><<<gBig, 128>>>(bQ, ffW2, ffb2, bK, M, DD, DD);

    // ---- prototypical scoring ----
    class_sum_kernel<<<BB, 256>>>(bK, lab, G, CNT);
    proto_out_kernel<<<dim3(NN, BB), 256>>>(bK, G, CNT, lab, out);
}

// round 5
// speedup vs baseline: 1.4672x; 1.1656x over previous
#include <cuda_runtime.h>
#include <cuda_bf16.h>
#include <math.h>
#include <stdint.h>

// Shapes: B=16, N=512, D=256, H=8, DK=32, C=16
#define BB 16
#define NN 512
#define DD 256
#define HH 8
#define DKH 32
#define CC 16

__device__ float g_bufQ[BB * NN * DD];
__device__ float g_bufK[BB * NN * DD];
__device__ float g_bufV[BB * NN * DD];
__device__ float g_bufO[BB * NN * DD];
__device__ float g_bufX[BB * NN * DD];
__device__ float g_aggrg[BB * DD];
__device__ float g_ares[BB * DD];
__device__ float g_rbias[BB * DD];
__device__ float g_G[BB * CC * DD];
__device__ float g_CNT[BB * CC];

__device__ __forceinline__ float gelu_f(float x) {
    return 0.5f * x * (1.0f + erff(x * 0.7071067811865475f));
}

// exp(x) on the FMA/ALU pipes (no MUFU). ~1.2e-7 rel error.
__device__ __forceinline__ float fast_exp(float x) {
    float y = x * 1.4426950408889634f;
    y = fmaxf(y, -126.0f);
    float f = rintf(y);
    float z = y - f;
    float p = 1.5403530393381609e-4f;
    p = fmaf(p, z, 1.3333558146428443e-3f);
    p = fmaf(p, z, 9.6181291076284772e-3f);
    p = fmaf(p, z, 5.5504108664821580e-2f);
    p = fmaf(p, z, 2.4022650695910072e-1f);
    p = fmaf(p, z, 6.9314718055994531e-1f);
    p = fmaf(p, z, 1.0f);
    int e = (int)f;
    float s = __int_as_float((e + 127) << 23);
    return p * s;
}

__device__ __forceinline__ uint32_t f2tf32(float x) {
    uint32_t u;
    asm("cvt.rna.tf32.f32 %0, %1;" : "=r"(u) : "f"(x));
    return u;
}

__device__ __forceinline__ void mma_tf32(float c[4],
    uint32_t a0, uint32_t a1, uint32_t a2, uint32_t a3,
    uint32_t b0, uint32_t b1)
{
    asm volatile(
        "mma.sync.aligned.m16n8k8.row.col.f32.tf32.tf32.f32 "
        "{%0,%1,%2,%3},{%4,%5,%6,%7},{%8,%9},{%0,%1,%2,%3};"
        : "+f"(c[0]), "+f"(c[1]), "+f"(c[2]), "+f"(c[3])
        : "r"(a0), "r"(a1), "r"(a2), "r"(a3), "r"(b0), "r"(b1));
}

// ---------------------------------------------------------------------------
// tf32 tensor-core GEMM: C[M,N] = act_out( act_in(A)@W + bias )
// Block 128x128, BK=16, 256 threads = 8 warps of 64x32 warp-tiles.
// A fragments: As[128][20] (pad-4 -> conflict-free 8-row x 4-col access).
// B fragments: Ws[16][136] (pad-8 -> conflict-free 4-row x 8-col access).
// ---------------------------------------------------------------------------
#define GBM 128
#define GBN 128
#define GBK 16

template <int AIN, int AOUT, int BMODE>
__global__ __launch_bounds__(256) void gemm_tf32_kernel(
    const float* __restrict__ A, const float* __restrict__ W,
    const float* __restrict__ bias, float* __restrict__ C,
    int M, int N, int K)
{
    __shared__ uint32_t As[GBM][GBK + 4];   // [128][20]
    __shared__ uint32_t Ws[GBK][GBN + 8];   // [16][136]

    const int t    = threadIdx.x;
    const int lane = t & 31;
    const int wid  = t >> 5;
    const int wm   = (wid & 1) * 64;        // warp m-offset: 0/64
    const int wn   = (wid >> 1) * 32;       // warp n-offset: 0/32/64/96
    const int bm   = blockIdx.x * GBM;
    const int bn   = blockIdx.y * GBN;

    float c[4][4][4];
    #pragma unroll
    for (int mt = 0; mt < 4; mt++)
        #pragma unroll
        for (int nt = 0; nt < 4; nt++)
            #pragma unroll
            for (int i = 0; i < 4; i++) c[mt][nt][i] = 0.0f;

    const int ar = t >> 1, ac = (t & 1) * 8;    // A: 128 rows x 16, 8 floats/thread
    const int wr = t >> 4, wc = (t & 15) * 8;   // W: 16 rows x 128, 8 floats/thread

    const int lq = lane >> 2;   // 0..7
    const int lr = lane & 3;    // 0..3

    for (int k0 = 0; k0 < K; k0 += GBK) {
        float4 a0 = make_float4(0.f,0.f,0.f,0.f), a1 = make_float4(0.f,0.f,0.f,0.f);
        if (bm + ar < M) {
            a0 = *(const float4*)&A[(size_t)(bm + ar) * K + k0 + ac];
            a1 = *(const float4*)&A[(size_t)(bm + ar) * K + k0 + ac + 4];
        }
        if (AIN) {
            a0.x = gelu_f(a0.x); a0.y = gelu_f(a0.y); a0.z = gelu_f(a0.z); a0.w = gelu_f(a0.w);
            a1.x = gelu_f(a1.x); a1.y = gelu_f(a1.y); a1.z = gelu_f(a1.z); a1.w = gelu_f(a1.w);
        }
        As[ar][ac + 0] = f2tf32(a0.x); As[ar][ac + 1] = f2tf32(a0.y);
        As[ar][ac + 2] = f2tf32(a0.z); As[ar][ac + 3] = f2tf32(a0.w);
        As[ar][ac + 4] = f2tf32(a1.x); As[ar][ac + 5] = f2tf32(a1.y);
        As[ar][ac + 6] = f2tf32(a1.z); As[ar][ac + 7] = f2tf32(a1.w);

        float4 w0 = *(const float4*)&W[(size_t)(k0 + wr) * N + bn + wc];
        float4 w1 = *(const float4*)&W[(size_t)(k0 + wr) * N + bn + wc + 4];
        Ws[wr][wc + 0] = f2tf32(w0.x); Ws[wr][wc + 1] = f2tf32(w0.y);
        Ws[wr][wc + 2] = f2tf32(w0.z); Ws[wr][wc + 3] = f2tf32(w0.w);
        Ws[wr][wc + 4] = f2tf32(w1.x); Ws[wr][wc + 5] = f2tf32(w1.y);
        Ws[wr][wc + 6] = f2tf32(w1.z); Ws[wr][wc + 7] = f2tf32(w1.w);

        __syncthreads();

        #pragma unroll
        for (int ks = 0; ks < GBK; ks += 8) {
            uint32_t af[4][4];
            #pragma unroll
            for (int mt = 0; mt < 4; mt++) {
                int r = wm + mt * 16 + lq;
                af[mt][0] = As[r    ][ks + lr];
                af[mt][1] = As[r + 8][ks + lr];
                af[mt][2] = As[r    ][ks + lr + 4];
                af[mt][3] = As[r + 8][ks + lr + 4];
            }
            uint32_t bf[4][2];
            #pragma unroll
            for (int nt = 0; nt < 4; nt++) {
                int nc = wn + nt * 8 + lq;
                bf[nt][0] = Ws[ks + lr    ][nc];
                bf[nt][1] = Ws[ks + lr + 4][nc];
            }
            #pragma unroll
            for (int mt = 0; mt < 4; mt++)
                #pragma unroll
                for (int nt = 0; nt < 4; nt++)
                    mma_tf32(c[mt][nt], af[mt][0], af[mt][1], af[mt][2], af[mt][3],
                             bf[nt][0], bf[nt][1]);
        }
        __syncthreads();
    }

    // epilogue
    #pragma unroll
    for (int mt = 0; mt < 4; mt++) {
        int row0 = bm + wm + mt * 16 + lq;
        int row1 = row0 + 8;
        #pragma unroll
        for (int nt = 0; nt < 4; nt++) {
            int col = bn + wn + nt * 8 + lr * 2;
            float v0 = c[mt][nt][0], v1 = c[mt][nt][1];
            float v2 = c[mt][nt][2], v3 = c[mt][nt][3];
            if (BMODE == 1) {
                float b0 = bias[col], b1 = bias[col + 1];
                v0 += b0; v1 += b1; v2 += b0; v3 += b1;
            }
            if (BMODE == 2) {
                if (row0 < M) {
                    const float* bb = bias + (size_t)(row0 >> 9) * N + col;
                    v0 += bb[0]; v1 += bb[1];
                }
                if (row1 < M) {
                    const float* bb = bias + (size_t)(row1 >> 9) * N + col;
                    v2 += bb[0]; v3 += bb[1];
                }
            }
            if (AOUT) { v0 = gelu_f(v0); v1 = gelu_f(v1); v2 = gelu_f(v2); v3 = gelu_f(v3); }
            if (row0 < M) *(float2*)&C[(size_t)row0 * N + col] = make_float2(v0, v1);
            if (row1 < M) *(float2*)&C[(size_t)row1 * N + col] = make_float2(v2, v3);
        }
    }
}

// ---------------------------------------------------------------------------
// Fused attention v4: 32 queries per block (2 CTAs/SM), 256 threads.
// smem (floats): qs[32][36] @0, ks[32][132] @1152, vs[128][36] @5376,
//                rs[32] @9984, sc[32][516] @10016; total 26528 fl = 103.6 KB.
// ---------------------------------------------------------------------------
#define SP 516
#define ATTN_SMEM_FLOATS 26528
#define ATTN_SMEM_BYTES  (ATTN_SMEM_FLOATS * 4)

__global__ __launch_bounds__(256) void attn_kernel(
    const float* __restrict__ Qp, const float* __restrict__ Kp,
    const float* __restrict__ Vp, float* __restrict__ Op)
{
    extern __shared__ float sm[];
    float* qs = sm;            // [32][36]  d-major Q (prescaled)
    float* ks = sm + 1152;     // [32][132] d-major K tile (128 keys)
    float* vs = sm + 5376;     // [128][36] row-major V tile
    float* rs = sm + 9984;     // [32] row sums
    float* sc = sm + 10016;    // [32][516]

    const int t  = threadIdx.x;
    const int qb = blockIdx.x * 32;
    const int h  = blockIdx.y;
    const int b  = blockIdx.z;
    const float scale = 0.17677669529663688f;  // 1/sqrt(32)

    const size_t baseQ  = ((size_t)(b * NN + qb)) * DD + h * DKH;
    const size_t baseKV = ((size_t)(b * NN)) * DD + h * DKH;

    // load Q transposed (d-major), prescaled: 32 rows x 32 d
    for (int i = t; i < 256; i += 256) {
        int r = i >> 3, cc = (i & 7) * 4;
        float4 q4 = *(const float4*)&Qp[baseQ + (size_t)r * DD + cc];
        qs[(cc + 0) * 36 + r] = q4.x * scale;
        qs[(cc + 1) * 36 + r] = q4.y * scale;
        qs[(cc + 2) * 36 + r] = q4.z * scale;
        qs[(cc + 3) * 36 + r] = q4.w * scale;
    }

    const int ty = t >> 5;   // warp 0..7 -> q rows ty*4 .. ty*4+3
    const int tx = t & 31;   // k group tx*4

    // ---- scores = Q @ K^T over 4 key-tiles of 128 ----
    for (int kt = 0; kt < 4; kt++) {
        const int kb = kt * 128;
        __syncthreads();
        for (int i = t; i < 1024; i += 256) {
            int r = i >> 3, cc = (i & 7) * 4;
            float4 k4 = *(const float4*)&Kp[baseKV + (size_t)(kb + r) * DD + cc];
            ks[(cc + 0) * 132 + r] = k4.x;
            ks[(cc + 1) * 132 + r] = k4.y;
            ks[(cc + 2) * 132 + r] = k4.z;
            ks[(cc + 3) * 132 + r] = k4.w;
        }
        __syncthreads();

        float acc[4][4];
        #pragma unroll
        for (int i = 0; i < 4; i++)
            #pragma unroll
            for (int j = 0; j < 4; j++) acc[i][j] = 0.0f;

        #pragma unroll
        for (int d = 0; d < 32; d++) {
            float4 a  = *(const float4*)&qs[d * 36 + ty * 4];       // warp-broadcast
            float4 bk = *(const float4*)&ks[d * 132 + tx * 4];
            float ar[4] = {a.x, a.y, a.z, a.w};
            #pragma unroll
            for (int i = 0; i < 4; i++) {
                acc[i][0] = fmaf(ar[i], bk.x, acc[i][0]);
                acc[i][1] = fmaf(ar[i], bk.y, acc[i][1]);
                acc[i][2] = fmaf(ar[i], bk.z, acc[i][2]);
                acc[i][3] = fmaf(ar[i], bk.w, acc[i][3]);
            }
        }
        #pragma unroll
        for (int i = 0; i < 4; i++)
            *(float4*)&sc[(ty * 4 + i) * SP + kb + tx * 4] =
                make_float4(acc[i][0], acc[i][1], acc[i][2], acc[i][3]);
    }
    __syncthreads();

    // ---- row softmax: max + exp (poly) + sums; normalize deferred ----
    {
        const int w = t >> 5, lane = t & 31;
        for (int r = w * 4; r < w * 4 + 4; r++) {
            float mx = -1e30f;
            for (int i = lane; i < 512; i += 32) mx = fmaxf(mx, sc[r * SP + i]);
            #pragma unroll
            for (int o = 16; o; o >>= 1) mx = fmaxf(mx, __shfl_xor_sync(0xFFFFFFFFu, mx, o));
            float s = 0.0f;
            for (int i = lane; i < 512; i += 32) {
                float e = fast_exp(sc[r * SP + i] - mx);
                sc[r * SP + i] = e;
                s += e;
            }
            #pragma unroll
            for (int o = 16; o; o >>= 1) s += __shfl_xor_sync(0xFFFFFFFFu, s, o);
            if (lane == 0) rs[r] = s;
        }
    }

    // ---- O = P @ V: 256 threads, 1q x 4d each ----
    const int q  = t >> 3;          // 0..31
    const int dg = (t & 7) * 4;     // 0..28
    float o[4] = {0, 0, 0, 0};

    for (int kt = 0; kt < 4; kt++) {
        const int kb = kt * 128;
        __syncthreads();
        for (int i = t; i < 1024; i += 256) {
            int r = i >> 3, cc = (i & 7) * 4;
            float4 v4 = *(const float4*)&Vp[baseKV + (size_t)(kb + r) * DD + cc];
            *(float4*)&vs[r * 36 + cc] = v4;
        }
        __syncthreads();

        const float* p = sc + (size_t)q * SP + kb;
        #pragma unroll 4
        for (int kk = 0; kk < 128; kk += 4) {
            float4 P = *(const float4*)&p[kk];   // broadcast across 8-lane group
            float4 v;
            v = *(const float4*)&vs[(kk + 0) * 36 + dg];
            o[0]=fmaf(P.x,v.x,o[0]); o[1]=fmaf(P.x,v.y,o[1]); o[2]=fmaf(P.x,v.z,o[2]); o[3]=fmaf(P.x,v.w,o[3]);
            v = *(const float4*)&vs[(kk + 1) * 36 + dg];
            o[0]=fmaf(P.y,v.x,o[0]); o[1]=fmaf(P.y,v.y,o[1]); o[2]=fmaf(P.y,v.z,o[2]); o[3]=fmaf(P.y,v.w,o[3]);
            v = *(const float4*)&vs[(kk + 2) * 36 + dg];
            o[0]=fmaf(P.z,v.x,o[0]); o[1]=fmaf(P.z,v.y,o[1]); o[2]=fmaf(P.z,v.z,o[2]); o[3]=fmaf(P.z,v.w,o[3]);
            v = *(const float4*)&vs[(kk + 3) * 36 + dg];
            o[0]=fmaf(P.w,v.x,o[0]); o[1]=fmaf(P.w,v.y,o[1]); o[2]=fmaf(P.w,v.z,o[2]); o[3]=fmaf(P.w,v.w,o[3]);
        }
    }
    float inv = 1.0f / rs[q];
    *(float4*)&Op[baseQ + (size_t)q * DD + dg] =
        make_float4(o[0]*inv, o[1]*inv, o[2]*inv, o[3]*inv);
}

// ---------------------------------------------------------------------------
__global__ __launch_bounds__(256) void colmean_gelu_kernel(
    const float* __restrict__ X, float* __restrict__ out)
{
    const int b = blockIdx.x;
    const int d = threadIdx.x;
    float s = 0.0f;
    const float* base = X + (size_t)b * NN * DD + d;
    for (int n = 0; n < NN; n++) s += base[(size_t)n * DD];
    out[b * DD + d] = gelu_f(s * (1.0f / (float)NN));
}

__global__ __launch_bounds__(256) void class_sum_kernel(
    const float* __restrict__ F, const int* __restrict__ lab,
    float* __restrict__ G, float* __restrict__ CNT)
{
    __shared__ float gs[CC * DD];
    __shared__ float cs[CC];
    const int b = blockIdx.x;
    const int t = threadIdx.x;
    for (int i = t; i < CC * DD; i += 256) gs[i] = 0.0f;
    if (t < CC) cs[t] = 0.0f;
    __syncthreads();
    for (int n = 0; n < NN; n++) {
        int c = lab[b * NN + n];
        gs[c * DD + t] += F[((size_t)b * NN + n) * DD + t];
        if (t == 0) cs[c] += 1.0f;
    }
    __syncthreads();
    for (int i = t; i < CC * DD; i += 256) G[(size_t)b * CC * DD + i] = gs[i];
    if (t < CC) CNT[b * CC + t] = cs[t];
}

__global__ __launch_bounds__(256) void proto_out_kernel(
    const float* __restrict__ F, const float* __restrict__ G,
    const float* __restrict__ CNT, const int* __restrict__ lab,
    float* __restrict__ out)
{
    __shared__ float fs[DD];
    const int n = blockIdx.x;
    const int b = blockIdx.y;
    const int t = threadIdx.x;
    fs[t] = F[((size_t)b * NN + n) * DD + t];
    __syncthreads();

    const int w = t >> 5, lane = t & 31;
    float sd = 0.0f;
    for (int i = lane; i < DD; i += 32) sd += fs[i] * fs[i];
    #pragma unroll
    for (int o = 16; o; o >>= 1) sd += __shfl_xor_sync(0xFFFFFFFFu, sd, o);

    const int labn = lab[b * NN + n];
    #pragma unroll
    for (int cc = 0; cc < 2; cc++) {
        const int c = w * 2 + cc;
        const float* g = G + (size_t)b * CC * DD + c * DD;
        float dp = 0.0f;
        for (int i = lane; i < DD; i += 32) dp += fs[i] * g[i];
        #pragma unroll
        for (int o = 16; o; o >>= 1) dp += __shfl_xor_sync(0xFFFFFFFFu, dp, o);
        if (lane == 0) {
            float same = (labn == c) ? 1.0f : 0.0f;
            out[((size_t)b * NN + n) * CC + c] =
                (dp - same * sd) / (CNT[b * CC + c] - same);
        }
    }
}

// ---------------------------------------------------------------------------
extern "C" void kernel_launch(void* const* d_in, const int* in_sizes, int n_in,
                              void* d_out, int out_size)
{
    const float* E    = (const float*)d_in[0];
    const int*   lab  = (const int*)  d_in[1];
    const float* Wq0  = (const float*)d_in[2];
    const float* Wk0  = (const float*)d_in[3];
    const float* Wv0  = (const float*)d_in[4];
    const float* Wo0  = (const float*)d_in[5];
    const float* Wq1  = (const float*)d_in[6];
    const float* Wk1  = (const float*)d_in[7];
    const float* Wv1  = (const float*)d_in[8];
    const float* Wo1  = (const float*)d_in[9];
    const float* resW = (const float*)d_in[10];
    const float* resb = (const float*)d_in[11];
    const float* ffW1 = (const float*)d_in[12];
    const float* ffb1 = (const float*)d_in[13];
    const float* ffW2 = (const float*)d_in[14];
    const float* ffb2 = (const float*)d_in[15];
    float* out = (float*)d_out;

    float *bQ, *bK, *bV, *bO, *bX, *aggrg, *ares, *rbias, *G, *CNT;
    cudaGetSymbolAddress((void**)&bQ,    g_bufQ);
    cudaGetSymbolAddress((void**)&bK,    g_bufK);
    cudaGetSymbolAddress((void**)&bV,    g_bufV);
    cudaGetSymbolAddress((void**)&bO,    g_bufO);
    cudaGetSymbolAddress((void**)&bX,    g_bufX);
    cudaGetSymbolAddress((void**)&aggrg, g_aggrg);
    cudaGetSymbolAddress((void**)&ares,  g_ares);
    cudaGetSymbolAddress((void**)&rbias, g_rbias);
    cudaGetSymbolAddress((void**)&G,     g_G);
    cudaGetSymbolAddress((void**)&CNT,   g_CNT);

    cudaFuncSetAttribute(attn_kernel,
                         cudaFuncAttributeMaxDynamicSharedMemorySize,
                         ATTN_SMEM_BYTES);

    const int M = BB * NN;                 // 8192
    dim3 gBig(M / GBM, DD / GBN);          // (64, 2)
    dim3 gSmall(1, DD / GBN);              // (1, 2)
    dim3 gAttn(NN / 32, HH, BB);           // (16, 8, 16)

    // ---- MHA 0 ----
    gemm_tf32_kernel<0, 0, 0><<<gBig, 256>>>(E, Wq0, nullptr, bQ, M, DD, DD);
    gemm_tf32_kernel<0, 0, 0><<<gBig, 256>>>(E, Wk0, nullptr, bK, M, DD, DD);
    gemm_tf32_kernel<0, 0, 0><<<gBig, 256>>>(E, Wv0, nullptr, bV, M, DD, DD);
    attn_kernel<<<gAttn, 256, ATTN_SMEM_BYTES>>>(bQ, bK, bV, bO);
    gemm_tf32_kernel<0, 1, 0><<<gBig, 256>>>(bO, Wo0, nullptr, bX, M, DD, DD);

    // ---- MHA 1 ----
    gemm_tf32_kernel<0, 0, 0><<<gBig, 256>>>(bX, Wq1, nullptr, bQ, M, DD, DD);
    gemm_tf32_kernel<0, 0, 0><<<gBig, 256>>>(bX, Wk1, nullptr, bK, M, DD, DD);
    gemm_tf32_kernel<0, 0, 0><<<gBig, 256>>>(bX, Wv1, nullptr, bV, M, DD, DD);
    attn_kernel<<<gAttn, 256, ATTN_SMEM_BYTES>>>(bQ, bK, bV, bO);
    gemm_tf32_kernel<0, 0, 0><<<gBig, 256>>>(bO, Wo1, nullptr, bX, M, DD, DD);

    // ---- aggregate path ----
    colmean_gelu_kernel<<<BB, 256>>>(bX, aggrg);
    gemm_tf32_kernel<0, 0, 1><<<gSmall, 256>>>(aggrg, resW, resb, ares, BB, DD, DD);
    gemm_tf32_kernel<1, 0, 1><<<gSmall, 256>>>(ares, ffW1, ffb1, rbias, BB, DD, DD);
    gemm_tf32_kernel<1, 1, 2><<<gBig, 256>>>(E, ffW1 + (size_t)DD * DD, rbias, bQ, M, DD, DD);
    gemm_tf32_kernel<0, 0, 1><<<gBig, 256>>>(bQ, ffW2, ffb2, bK, M, DD, DD);

    // ---- prototypical scoring ----
    class_sum_kernel<<<BB, 256>>>(bK, lab, G, CNT);
    proto_out_kernel<<<dim3(NN, BB), 256>>>(bK, G, CNT, lab, out);
}